// round 12
// baseline (speedup 1.0000x reference)
#include <cuda_runtime.h>
#include <cuda_fp16.h>
#include <mma.h>
#include <cstdint>

using namespace nvcuda;

#define T_STEPS 512
#define BATCH   256
#define N1      512
#define N2      256
#define N3      64
#define N4      784

// Scratch (no allocations allowed)
__device__ __half  g_Wh[2 * N2 * N1];                 // W_lif 2-way fp16 split: [s][i][n]
__device__ __half  g_spkh[(size_t)T_STEPS * BATCH * N2];  // spikes as fp16 (64 MB)
__device__ float   g_WliT[N1 * N2];                   // W_li^T : [k][j]
__device__ float   g_S[BATCH * N1];                   // weighted spike sums

__device__ __forceinline__ uint32_t smem_u32(const void* p) {
    uint32_t a;
    asm("{ .reg .u64 t; cvta.to.shared.u64 t, %1; cvt.u32.u64 %0, t; }" : "=r"(a) : "l"(p));
    return a;
}
#define BAR_SYNC(id, cnt)   asm volatile("bar.sync %0, %1;"   :: "r"(id), "r"(cnt) : "memory")
#define BAR_ARRIVE(id, cnt) asm volatile("bar.arrive %0, %1;" :: "r"(id), "r"(cnt) : "memory")

// ---------------------------------------------------------------------------
// Kernel 1: split W_lif[n][i] into 2 fp16 components stored as [s][i][n]
// ---------------------------------------------------------------------------
__global__ void __launch_bounds__(256) wsplit_kernel(const float* __restrict__ W) {
    int idx = blockIdx.x * 256 + threadIdx.x;        // over i*512 + n
    int i = idx >> 9, n = idx & 511;
    float w = W[n * N2 + i];
    __half h1 = __float2half_rn(w);
    float r = w - __half2float(h1);
    __half h2 = __float2half_rn(r);
    g_Wh[idx]            = h1;                       // split 0
    g_Wh[N2 * N1 + idx]  = h2;                       // split 1
}

// ---------------------------------------------------------------------------
// Kernel 2: convert spikes fp32 -> fp16 (exact: values are 0/1)
// ---------------------------------------------------------------------------
__global__ void __launch_bounds__(256) spkconv_kernel(const float* __restrict__ spk) {
    size_t idx = (size_t)blockIdx.x * 256 + threadIdx.x;   // x4 elems
    float4 v = reinterpret_cast<const float4*>(spk)[idx];
    __half2 a = __floats2half2_rn(v.x, v.y);
    __half2 b = __floats2half2_rn(v.z, v.w);
    uint32_t* dst = reinterpret_cast<uint32_t*>(g_spkh);
    dst[idx * 2]     = *reinterpret_cast<uint32_t*>(&a);
    dst[idx * 2 + 1] = *reinterpret_cast<uint32_t*>(&b);
}

// ---------------------------------------------------------------------------
// Kernel 3: generic 32x32 tiled transpose (for W_li)
// ---------------------------------------------------------------------------
__global__ void transpose_kernel(const float* __restrict__ src, float* __restrict__ dst,
                                 int rows, int cols) {
    __shared__ float tile[32][33];
    int bx = blockIdx.x, by = blockIdx.y;
    int tx = threadIdx.x, ty = threadIdx.y;
    #pragma unroll
    for (int r = ty; r < 32; r += 8)
        tile[r][tx] = src[(size_t)(by * 32 + r) * cols + bx * 32 + tx];
    __syncthreads();
    #pragma unroll
    for (int r = ty; r < 32; r += 8)
        dst[(size_t)(bx * 32 + r) * rows + by * 32 + tx] = tile[tx][r];
}

// ---------------------------------------------------------------------------
// smem layout (bytes), per block (N-chunk = 64 neurons):
//   W resident : [2][256][72] fp16 = 73728            @ 0
//   A buffers  : 2 x [128][72] fp16 = 2 x 18432       @ 73728, 92160
//   C buffers  : 2 x [64][132] fp32 (col-major [n][t]) @ 110592, 144384
//   total = 178176  -> 1 block/SM, 10 warps (8 MMA + 2 scan)
// ---------------------------------------------------------------------------
#define W_BYTES     73728
#define A_OFF(buf)  (W_BYTES + (buf) * 18432)
#define C_OFF(buf)  (110592 + (buf) * 33792)
#define SMEM_BYTES  178176

// named barriers
#define BAR_MMA        1      // producer-only A/W handshakes (count 256)
#define BAR_FULL(buf)  (2 + (buf))   // count 320
#define BAR_EMPTY(buf) (4 + (buf))   // count 320

// async-load one A k-chunk: spk[t0..t0+128, kc*64..+64] fp16 (16 KB), 256 thr
__device__ __forceinline__ void prefetch_A(int b, int t0, int kc,
                                           uint32_t smA, int tid) {
    #pragma unroll
    for (int j = 0; j < 4; j++) {
        int c16 = tid + j * 256;
        int r = c16 >> 3, cc = c16 & 7;
        const char* g = reinterpret_cast<const char*>(g_spkh)
            + ((((size_t)(t0 + r)) * BATCH + b) * N2 + kc * 64 + cc * 8) * 2;
        asm volatile("cp.async.cg.shared.global [%0], [%1], 16;"
                     :: "r"(smA + r * 144 + cc * 16), "l"(g));
    }
    asm volatile("cp.async.commit_group;" ::: "memory");
}

// ---------------------------------------------------------------------------
// Kernel 4: warp-specialized WMMA GEMM + pipelined LIF scan.
// Warps 0-7 (256 thr): W-resident GEMM producing C tiles (double-buffered).
// Warps 8-9 (64 thr): consume C tiles, run the sequential LIF scan.
// ---------------------------------------------------------------------------
__global__ void __launch_bounds__(320, 1) mma_scan_kernel(const float* __restrict__ b_lif) {
    extern __shared__ char sm[];
    const __half* Wsm = reinterpret_cast<const __half*>(sm);   // [2][256][72]

    const int tid = threadIdx.x;
    const int b      = blockIdx.x >> 3;
    const int nchunk = blockIdx.x & 7;
    const int nbase  = nchunk * 64;
    const uint32_t smbase = smem_u32(sm);

    const float inv_beta = 1.0f / 0.95f;
    const float wnorm    = 1.0f / 25.6f;

    if (tid < 256) {
        // ================= PRODUCERS: GEMM =================
        const int warp = tid >> 5;
        const int wm = warp >> 1, wn = warp & 1;

        // load resident W chunk: [s][i=256][n=64], stride 72 halves
        #pragma unroll
        for (int j = 0; j < 16; j++) {
            int c = tid + j * 256;                    // 4096 x 16B chunks
            int s = c >> 11, rem = c & 2047;
            int i = rem >> 3, cc = rem & 7;
            const char* g = reinterpret_cast<const char*>(g_Wh)
                + (((size_t)(s * N2 + i)) * N1 + nbase + cc * 8) * 2;
            asm volatile("cp.async.cg.shared.global [%0], [%1], 16;"
                         :: "r"(smbase + (uint32_t)(s * 36864 + i * 144 + cc * 16)), "l"(g));
        }
        asm volatile("cp.async.commit_group;" ::: "memory");
        asm volatile("cp.async.wait_group 0;" ::: "memory");
        BAR_SYNC(BAR_MMA, 256);

        wmma::fragment<wmma::accumulator, 16, 16, 16, float> c[2][2];

        for (int tt = 0; tt < 4; tt++) {
            const int t0 = tt * 128;
            #pragma unroll
            for (int mi = 0; mi < 2; mi++)
                #pragma unroll
                for (int ni = 0; ni < 2; ni++)
                    wmma::fill_fragment(c[mi][ni], 0.0f);

            prefetch_A(b, t0, 0, smbase + A_OFF(0), tid);

            #pragma unroll
            for (int kc = 0; kc < 4; kc++) {
                const int cur = kc & 1;
                BAR_SYNC(BAR_MMA, 256);       // A buf[cur^1] consumed by prev MMA
                if (kc < 3) {
                    prefetch_A(b, t0, kc + 1, smbase + A_OFF(cur ^ 1), tid);
                    asm volatile("cp.async.wait_group 1;" ::: "memory");
                } else {
                    asm volatile("cp.async.wait_group 0;" ::: "memory");
                }
                BAR_SYNC(BAR_MMA, 256);       // A buf[cur] visible

                const __half* Asm = reinterpret_cast<const __half*>(sm + A_OFF(cur));

                #pragma unroll
                for (int ks = 0; ks < 4; ks++) {
                    wmma::fragment<wmma::matrix_a, 16, 16, 16, __half, wmma::row_major> a[2];
                    #pragma unroll
                    for (int mi = 0; mi < 2; mi++)
                        wmma::load_matrix_sync(a[mi],
                            Asm + (wm * 32 + mi * 16) * 72 + ks * 16, 72);
                    #pragma unroll
                    for (int s = 0; s < 2; s++) {
                        #pragma unroll
                        for (int ni = 0; ni < 2; ni++) {
                            wmma::fragment<wmma::matrix_b, 16, 16, 16, __half, wmma::row_major> bf;
                            wmma::load_matrix_sync(bf,
                                Wsm + s * 18432 + (kc * 64 + ks * 16) * 72 + wn * 32 + ni * 16, 72);
                            #pragma unroll
                            for (int mi = 0; mi < 2; mi++)
                                wmma::mma_sync(c[mi][ni], a[mi], bf, c[mi][ni]);
                        }
                    }
                }
            }

            // wait until scan finished with this C buffer (buffers free for tt<2)
            if (tt >= 2) BAR_SYNC(BAR_EMPTY(tt & 1), 320);

            // store C col-major: element (t, n) -> Cb[n*132 + t]
            float* Cb = reinterpret_cast<float*>(sm + C_OFF(tt & 1));
            #pragma unroll
            for (int mi = 0; mi < 2; mi++)
                #pragma unroll
                for (int ni = 0; ni < 2; ni++)
                    wmma::store_matrix_sync(
                        Cb + (wn * 32 + ni * 16) * 132 + (wm * 32 + mi * 16),
                        c[mi][ni], 132, wmma::mem_col_major);
            __threadfence_block();
            BAR_ARRIVE(BAR_FULL(tt & 1), 320);
        }
    } else {
        // ================= CONSUMERS: LIF scan =================
        const int stid = tid - 256;                  // 0..63, one neuron each
        const float bl = b_lif[nbase + stid];

        float p = 0.95f;                             // beta_li^T via 9 squarings
        #pragma unroll
        for (int k = 0; k < 9; k++) p *= p;

        float mem = 0.0f, S = 0.0f;

        for (int tt = 0; tt < 4; tt++) {
            BAR_SYNC(BAR_FULL(tt & 1), 320);
            const float4* Crow = reinterpret_cast<const float4*>(
                sm + C_OFF(tt & 1) + (size_t)stid * 528);   // 132 floats/row
            #pragma unroll 8
            for (int q = 0; q < 32; q++) {
                float4 v = Crow[q];
                #pragma unroll
                for (int e = 0; e < 4; e++) {
                    float cur = ((e == 0) ? v.x : (e == 1) ? v.y : (e == 2) ? v.z : v.w) + bl;
                    float rst = (mem > 1.0f) ? 1.0f : 0.0f;
                    mem = 0.9f * mem + cur - rst;
                    float wt = (1.0f - p) * wnorm;
                    if (mem > 1.0f) S += wt;
                    p *= inv_beta;
                }
            }
            BAR_ARRIVE(BAR_EMPTY(tt & 1), 320);
        }
        g_S[(size_t)b * N1 + nbase + stid] = S;
    }
}

// ---------------------------------------------------------------------------
// Kernel 5: fused tail — one block per batch row (R6-proven).
// ---------------------------------------------------------------------------
__global__ void __launch_bounds__(256) tail_kernel(
    const float* __restrict__ b_li,
    const float* __restrict__ W1,  const float* __restrict__ b1,
    const float* __restrict__ W2,  const float* __restrict__ b2,
    const float* __restrict__ ln_g, const float* __restrict__ ln_b,
    float* __restrict__ out)
{
    __shared__ float sS[N1];
    __shared__ float sx[N2];
    __shared__ float sh[N3];
    __shared__ float sy[N4];
    __shared__ float sred[16];
    const int b = blockIdx.x, tid = threadIdx.x;
    const int warp = tid >> 5, lane = tid & 31;

    sS[tid]       = g_S[b * N1 + tid];
    sS[tid + 256] = g_S[b * N1 + 256 + tid];
    __syncthreads();

    float pw = 0.95f;
    #pragma unroll
    for (int k = 0; k < 9; k++) pw *= pw;
    const float SW = (512.0f - 19.0f * (1.0f - pw)) / 25.6f;

    {
        float acc0 = SW * b_li[tid], acc1 = 0.0f;
        const float* wt = g_WliT + tid;
        #pragma unroll 8
        for (int k = 0; k < N1; k += 2) {
            acc0 = fmaf(sS[k],     wt[(size_t)k       * N2], acc0);
            acc1 = fmaf(sS[k + 1], wt[(size_t)(k + 1) * N2], acc1);
        }
        sx[tid] = acc0 + acc1;
    }
    __syncthreads();

    const float2* sx2 = reinterpret_cast<const float2*>(sx);
    #pragma unroll
    for (int oo = 0; oo < 8; oo++) {
        int o = warp * 8 + oo;
        const float2* wrow = reinterpret_cast<const float2*>(W1 + (size_t)o * N2);
        float acc = 0.0f;
        #pragma unroll
        for (int it = 0; it < 4; it++) {
            int k2 = it * 32 + lane;
            float2 wv = wrow[k2], xv = sx2[k2];
            acc += wv.x * xv.x + wv.y * xv.y;
        }
        #pragma unroll
        for (int d = 16; d > 0; d >>= 1) acc += __shfl_xor_sync(0xffffffffu, acc, d);
        if (lane == 0) sh[o] = fmaxf(acc + b1[o], 0.0f);
    }
    __syncthreads();

    const float2* hh = reinterpret_cast<const float2*>(sh);
    float2 hv = hh[lane];
    for (int g = 0; g < 98; g++) {
        int o = warp + g * 8;
        const float2* w2 = reinterpret_cast<const float2*>(W2 + (size_t)o * N3);
        float2 wv = w2[lane];
        float acc = wv.x * hv.x + wv.y * hv.y;
        #pragma unroll
        for (int d = 16; d > 0; d >>= 1) acc += __shfl_xor_sync(0xffffffffu, acc, d);
        if (lane == 0) sy[o] = acc + b2[o];
    }
    __syncthreads();

    float s = 0.0f;
    for (int k = tid; k < N4; k += 256) s += sy[k];
    #pragma unroll
    for (int o = 16; o > 0; o >>= 1) s += __shfl_xor_sync(0xffffffffu, s, o);
    if (lane == 0) sred[warp] = s;
    __syncthreads();
    if (tid < 32) {
        float v = (tid < 8) ? sred[tid] : 0.0f;
        #pragma unroll
        for (int o = 4; o > 0; o >>= 1) v += __shfl_xor_sync(0xffffffffu, v, o);
        if (tid == 0) sred[0] = v;
    }
    __syncthreads();
    const float mu = sred[0] / (float)N4;
    __syncthreads();

    float s2 = 0.0f;
    for (int k = tid; k < N4; k += 256) { float d = sy[k] - mu; s2 += d * d; }
    #pragma unroll
    for (int o = 16; o > 0; o >>= 1) s2 += __shfl_xor_sync(0xffffffffu, s2, o);
    if (lane == 0) sred[warp] = s2;
    __syncthreads();
    if (tid < 32) {
        float v = (tid < 8) ? sred[tid] : 0.0f;
        #pragma unroll
        for (int o = 4; o > 0; o >>= 1) v += __shfl_xor_sync(0xffffffffu, v, o);
        if (tid == 0) sred[0] = v;
    }
    __syncthreads();
    const float var  = sred[0] / (float)N4;
    const float rstd = rsqrtf(var + 1e-5f);

    for (int k = tid; k < N4; k += 256)
        out[(size_t)b * N4 + k] = (sy[k] - mu) * rstd * ln_g[k] + ln_b[k];
}

// ---------------------------------------------------------------------------
extern "C" void kernel_launch(void* const* d_in, const int* in_sizes, int n_in,
                              void* d_out, int out_size) {
    const float* spk   = (const float*)d_in[0];
    const float* W_lif = (const float*)d_in[1];
    const float* b_lif = (const float*)d_in[2];
    const float* W_li  = (const float*)d_in[3];
    const float* b_li  = (const float*)d_in[4];
    const float* W1    = (const float*)d_in[5];
    const float* b1    = (const float*)d_in[6];
    const float* W2    = (const float*)d_in[7];
    const float* b2    = (const float*)d_in[8];
    const float* ln_g  = (const float*)d_in[9];
    const float* ln_b  = (const float*)d_in[10];
    float* out = (float*)d_out;

    cudaFuncSetAttribute(mma_scan_kernel, cudaFuncAttributeMaxDynamicSharedMemorySize, SMEM_BYTES);

    float* d_WliT; cudaGetSymbolAddress((void**)&d_WliT, g_WliT);

    wsplit_kernel<<<N2 * N1 / 256, 256>>>(W_lif);
    spkconv_kernel<<<(int)((size_t)T_STEPS * BATCH * N2 / 4 / 256), 256>>>(spk);
    transpose_kernel<<<dim3(16, 8), dim3(32, 8)>>>(W_li, d_WliT, N2, N1);
    mma_scan_kernel<<<BATCH * 8, 320, SMEM_BYTES>>>(b_lif);
    tail_kernel<<<BATCH, 256>>>(b_li, W1, b1, W2, b2, ln_g, ln_b, out);
}

// round 13
// speedup vs baseline: 1.1624x; 1.1624x over previous
#include <cuda_runtime.h>
#include <cuda_fp16.h>
#include <mma.h>
#include <cstdint>

using namespace nvcuda;

#define T_STEPS 512
#define BATCH   256
#define N1      512
#define N2      256
#define N3      64
#define N4      784

// Scratch (no allocations allowed)
__device__ __half  g_Wh[2 * N2 * N1];                 // W_lif 2-way fp16 split: [s][i][n]
__device__ __half  g_spkh[(size_t)T_STEPS * BATCH * N2];  // spikes as fp16 (64 MB)
__device__ float   g_WliT[N1 * N2];                   // W_li^T : [k][j]
__device__ float   g_S[BATCH * N1];                   // weighted spike sums

__device__ __forceinline__ uint32_t smem_u32(const void* p) {
    uint32_t a;
    asm("{ .reg .u64 t; cvta.to.shared.u64 t, %1; cvt.u32.u64 %0, t; }" : "=r"(a) : "l"(p));
    return a;
}

// ---------------------------------------------------------------------------
// Kernel 1: split W_lif[n][i] into 2 fp16 components stored as [s][i][n]
// ---------------------------------------------------------------------------
__global__ void __launch_bounds__(256) wsplit_kernel(const float* __restrict__ W) {
    int idx = blockIdx.x * 256 + threadIdx.x;        // over i*512 + n
    int i = idx >> 9, n = idx & 511;
    float w = W[n * N2 + i];
    __half h1 = __float2half_rn(w);
    float r = w - __half2float(h1);
    __half h2 = __float2half_rn(r);
    g_Wh[idx]            = h1;                       // split 0
    g_Wh[N2 * N1 + idx]  = h2;                       // split 1
}

// ---------------------------------------------------------------------------
// Kernel 2: convert spikes fp32 -> fp16 (exact: values are 0/1)
// ---------------------------------------------------------------------------
__global__ void __launch_bounds__(256) spkconv_kernel(const float* __restrict__ spk) {
    size_t idx = (size_t)blockIdx.x * 256 + threadIdx.x;   // x4 elems
    float4 v = reinterpret_cast<const float4*>(spk)[idx];
    __half2 a = __floats2half2_rn(v.x, v.y);
    __half2 b = __floats2half2_rn(v.z, v.w);
    uint32_t* dst = reinterpret_cast<uint32_t*>(g_spkh);
    dst[idx * 2]     = *reinterpret_cast<uint32_t*>(&a);
    dst[idx * 2 + 1] = *reinterpret_cast<uint32_t*>(&b);
}

// ---------------------------------------------------------------------------
// Kernel 3: generic 32x32 tiled transpose (for W_li)
// ---------------------------------------------------------------------------
__global__ void transpose_kernel(const float* __restrict__ src, float* __restrict__ dst,
                                 int rows, int cols) {
    __shared__ float tile[32][33];
    int bx = blockIdx.x, by = blockIdx.y;
    int tx = threadIdx.x, ty = threadIdx.y;
    #pragma unroll
    for (int r = ty; r < 32; r += 8)
        tile[r][tx] = src[(size_t)(by * 32 + r) * cols + bx * 32 + tx];
    __syncthreads();
    #pragma unroll
    for (int r = ty; r < 32; r += 8)
        dst[(size_t)(bx * 32 + r) * rows + by * 32 + tx] = tile[tx][r];
}

// ---------------------------------------------------------------------------
// smem layout (bytes), per block (N-chunk = 64 neurons):
//   W resident : [2][256][72] fp16 = 73728            @ 0
//   A buffers  : 2 x [128][72] fp16 = 2 x 18432       @ 73728, 92160
//   C overlay  : [64][132] fp32 (col-major [n][t]) = 33792 @ 73728 (over A)
//   total = 110592  -> 2 blocks/SM, 4 MMA warps each (warp tile 64t x 32n)
// ---------------------------------------------------------------------------
#define W_BYTES     73728
#define A_OFF(buf)  (W_BYTES + (buf) * 18432)
#define SMEM_BYTES  110592

// async-load one A k-chunk: spk[t0..t0+128, kc*64..+64] fp16 (16 KB), 128 thr
__device__ __forceinline__ void prefetch_A(int b, int t0, int kc,
                                           uint32_t smA, int tid) {
    #pragma unroll
    for (int j = 0; j < 8; j++) {
        int c16 = tid + j * 128;
        int r = c16 >> 3, cc = c16 & 7;
        const char* g = reinterpret_cast<const char*>(g_spkh)
            + ((((size_t)(t0 + r)) * BATCH + b) * N2 + kc * 64 + cc * 8) * 2;
        asm volatile("cp.async.cg.shared.global [%0], [%1], 16;"
                     :: "r"(smA + r * 144 + cc * 16), "l"(g));
    }
    asm volatile("cp.async.commit_group;" ::: "memory");
}

// ---------------------------------------------------------------------------
// Kernel 4: WMMA current GEMM (W resident in smem) + fused LIF scan.
// Block = (batch b, 64-neuron chunk), 128 threads = 4 warps (2m x 2n),
// warp C tile 64t x 32n (B fragments reused 4x across mi -> 2/3 the LDSM
// traffic of the 32x32 layout). 2 blocks/SM for phase overlap.
// ---------------------------------------------------------------------------
__global__ void __launch_bounds__(128, 2) mma_scan_kernel(const float* __restrict__ b_lif) {
    extern __shared__ char sm[];
    const __half* Wsm = reinterpret_cast<const __half*>(sm);   // [2][256][72]
    float* Csm = reinterpret_cast<float*>(sm + W_BYTES);       // [64][132] col-major overlay

    const int tid  = threadIdx.x;
    const int warp = tid >> 5;
    const int b      = blockIdx.x >> 3;
    const int nchunk = blockIdx.x & 7;
    const int nbase  = nchunk * 64;
    const int wm = warp >> 1, wn = warp & 1;     // 2m x 2n

    const uint32_t smbase = smem_u32(sm);

    // ---- load resident W chunk: both splits, [s][i=256][n=64], stride 72 halves
    #pragma unroll
    for (int j = 0; j < 32; j++) {
        int c = tid + j * 128;                    // 4096 x 16B chunks
        int s = c >> 11, rem = c & 2047;
        int i = rem >> 3, cc = rem & 7;
        const char* g = reinterpret_cast<const char*>(g_Wh)
            + (((size_t)(s * N2 + i)) * N1 + nbase + cc * 8) * 2;
        asm volatile("cp.async.cg.shared.global [%0], [%1], 16;"
                     :: "r"(smbase + (uint32_t)(s * 36864 + i * 144 + cc * 16)), "l"(g));
    }
    asm volatile("cp.async.commit_group;" ::: "memory");
    asm volatile("cp.async.wait_group 0;" ::: "memory");
    __syncthreads();

    wmma::fragment<wmma::accumulator, 16, 16, 16, float> c[4][2];

    const float bl = (tid < 64) ? b_lif[nbase + tid] : 0.0f;
    const float inv_beta = 1.0f / 0.95f;
    const float wnorm    = 1.0f / 25.6f;
    float p = 0.95f;                                 // beta_li^T via 9 squarings
    #pragma unroll
    for (int k = 0; k < 9; k++) p *= p;

    float mem = 0.0f, S = 0.0f;

    for (int tt = 0; tt < 4; tt++) {
        const int t0 = tt * 128;
        #pragma unroll
        for (int mi = 0; mi < 4; mi++)
            #pragma unroll
            for (int ni = 0; ni < 2; ni++)
                wmma::fill_fragment(c[mi][ni], 0.0f);

        prefetch_A(b, t0, 0, smbase + A_OFF(0), tid);

        #pragma unroll
        for (int kc = 0; kc < 4; kc++) {
            const int cur = kc & 1;
            __syncthreads();              // A buf[cur^1] consumed by prev MMA
            if (kc < 3) {
                prefetch_A(b, t0, kc + 1, smbase + A_OFF(cur ^ 1), tid);
                asm volatile("cp.async.wait_group 1;" ::: "memory");
            } else {
                asm volatile("cp.async.wait_group 0;" ::: "memory");
            }
            __syncthreads();              // A buf[cur] visible

            const __half* Asm = reinterpret_cast<const __half*>(sm + A_OFF(cur));

            #pragma unroll
            for (int ks = 0; ks < 4; ks++) {
                wmma::fragment<wmma::matrix_a, 16, 16, 16, __half, wmma::row_major> a[4];
                #pragma unroll
                for (int mi = 0; mi < 4; mi++)
                    wmma::load_matrix_sync(a[mi],
                        Asm + (wm * 64 + mi * 16) * 72 + ks * 16, 72);
                #pragma unroll
                for (int s = 0; s < 2; s++) {
                    #pragma unroll
                    for (int ni = 0; ni < 2; ni++) {
                        wmma::fragment<wmma::matrix_b, 16, 16, 16, __half, wmma::row_major> bf;
                        wmma::load_matrix_sync(bf,
                            Wsm + s * 18432 + (kc * 64 + ks * 16) * 72 + wn * 32 + ni * 16, 72);
                        #pragma unroll
                        for (int mi = 0; mi < 4; mi++)
                            wmma::mma_sync(c[mi][ni], a[mi], bf, c[mi][ni]);
                    }
                }
            }
        }
        __syncthreads();                             // GEMM done; A region free

        // store C col-major: element (t, n) -> Csm[n*132 + t]
        #pragma unroll
        for (int mi = 0; mi < 4; mi++)
            #pragma unroll
            for (int ni = 0; ni < 2; ni++)
                wmma::store_matrix_sync(
                    Csm + (wn * 32 + ni * 16) * 132 + (wm * 64 + mi * 16),
                    c[mi][ni], 132, wmma::mem_col_major);
        __syncthreads();

        // LIF scan: threads 0-63 own a neuron; 32 contiguous float4 reads
        if (tid < 64) {
            const float4* Crow = reinterpret_cast<const float4*>(Csm + (size_t)tid * 132);
            #pragma unroll 8
            for (int q = 0; q < 32; q++) {
                float4 v = Crow[q];
                #pragma unroll
                for (int e = 0; e < 4; e++) {
                    float cur = ((e == 0) ? v.x : (e == 1) ? v.y : (e == 2) ? v.z : v.w) + bl;
                    float rst = (mem > 1.0f) ? 1.0f : 0.0f;
                    mem = 0.9f * mem + cur - rst;
                    float wt = (1.0f - p) * wnorm;
                    if (mem > 1.0f) S += wt;
                    p *= inv_beta;
                }
            }
        }
        __syncthreads();                             // scan done before next A loads
    }

    if (tid < 64)
        g_S[(size_t)b * N1 + nbase + tid] = S;
}

// ---------------------------------------------------------------------------
// Kernel 5: fused tail — one block per batch row (R6-proven).
// ---------------------------------------------------------------------------
__global__ void __launch_bounds__(256) tail_kernel(
    const float* __restrict__ b_li,
    const float* __restrict__ W1,  const float* __restrict__ b1,
    const float* __restrict__ W2,  const float* __restrict__ b2,
    const float* __restrict__ ln_g, const float* __restrict__ ln_b,
    float* __restrict__ out)
{
    __shared__ float sS[N1];
    __shared__ float sx[N2];
    __shared__ float sh[N3];
    __shared__ float sy[N4];
    __shared__ float sred[16];
    const int b = blockIdx.x, tid = threadIdx.x;
    const int warp = tid >> 5, lane = tid & 31;

    sS[tid]       = g_S[b * N1 + tid];
    sS[tid + 256] = g_S[b * N1 + 256 + tid];
    __syncthreads();

    float pw = 0.95f;
    #pragma unroll
    for (int k = 0; k < 9; k++) pw *= pw;
    const float SW = (512.0f - 19.0f * (1.0f - pw)) / 25.6f;

    {
        float acc0 = SW * b_li[tid], acc1 = 0.0f;
        const float* wt = g_WliT + tid;
        #pragma unroll 8
        for (int k = 0; k < N1; k += 2) {
            acc0 = fmaf(sS[k],     wt[(size_t)k       * N2], acc0);
            acc1 = fmaf(sS[k + 1], wt[(size_t)(k + 1) * N2], acc1);
        }
        sx[tid] = acc0 + acc1;
    }
    __syncthreads();

    const float2* sx2 = reinterpret_cast<const float2*>(sx);
    #pragma unroll
    for (int oo = 0; oo < 8; oo++) {
        int o = warp * 8 + oo;
        const float2* wrow = reinterpret_cast<const float2*>(W1 + (size_t)o * N2);
        float acc = 0.0f;
        #pragma unroll
        for (int it = 0; it < 4; it++) {
            int k2 = it * 32 + lane;
            float2 wv = wrow[k2], xv = sx2[k2];
            acc += wv.x * xv.x + wv.y * xv.y;
        }
        #pragma unroll
        for (int d = 16; d > 0; d >>= 1) acc += __shfl_xor_sync(0xffffffffu, acc, d);
        if (lane == 0) sh[o] = fmaxf(acc + b1[o], 0.0f);
    }
    __syncthreads();

    const float2* hh = reinterpret_cast<const float2*>(sh);
    float2 hv = hh[lane];
    for (int g = 0; g < 98; g++) {
        int o = warp + g * 8;
        const float2* w2 = reinterpret_cast<const float2*>(W2 + (size_t)o * N3);
        float2 wv = w2[lane];
        float acc = wv.x * hv.x + wv.y * hv.y;
        #pragma unroll
        for (int d = 16; d > 0; d >>= 1) acc += __shfl_xor_sync(0xffffffffu, acc, d);
        if (lane == 0) sy[o] = acc + b2[o];
    }
    __syncthreads();

    float s = 0.0f;
    for (int k = tid; k < N4; k += 256) s += sy[k];
    #pragma unroll
    for (int o = 16; o > 0; o >>= 1) s += __shfl_xor_sync(0xffffffffu, s, o);
    if (lane == 0) sred[warp] = s;
    __syncthreads();
    if (tid < 32) {
        float v = (tid < 8) ? sred[tid] : 0.0f;
        #pragma unroll
        for (int o = 4; o > 0; o >>= 1) v += __shfl_xor_sync(0xffffffffu, v, o);
        if (tid == 0) sred[0] = v;
    }
    __syncthreads();
    const float mu = sred[0] / (float)N4;
    __syncthreads();

    float s2 = 0.0f;
    for (int k = tid; k < N4; k += 256) { float d = sy[k] - mu; s2 += d * d; }
    #pragma unroll
    for (int o = 16; o > 0; o >>= 1) s2 += __shfl_xor_sync(0xffffffffu, s2, o);
    if (lane == 0) sred[warp] = s2;
    __syncthreads();
    if (tid < 32) {
        float v = (tid < 8) ? sred[tid] : 0.0f;
        #pragma unroll
        for (int o = 4; o > 0; o >>= 1) v += __shfl_xor_sync(0xffffffffu, v, o);
        if (tid == 0) sred[0] = v;
    }
    __syncthreads();
    const float var  = sred[0] / (float)N4;
    const float rstd = rsqrtf(var + 1e-5f);

    for (int k = tid; k < N4; k += 256)
        out[(size_t)b * N4 + k] = (sy[k] - mu) * rstd * ln_g[k] + ln_b[k];
}

// ---------------------------------------------------------------------------
extern "C" void kernel_launch(void* const* d_in, const int* in_sizes, int n_in,
                              void* d_out, int out_size) {
    const float* spk   = (const float*)d_in[0];
    const float* W_lif = (const float*)d_in[1];
    const float* b_lif = (const float*)d_in[2];
    const float* W_li  = (const float*)d_in[3];
    const float* b_li  = (const float*)d_in[4];
    const float* W1    = (const float*)d_in[5];
    const float* b1    = (const float*)d_in[6];
    const float* W2    = (const float*)d_in[7];
    const float* b2    = (const float*)d_in[8];
    const float* ln_g  = (const float*)d_in[9];
    const float* ln_b  = (const float*)d_in[10];
    float* out = (float*)d_out;

    cudaFuncSetAttribute(mma_scan_kernel, cudaFuncAttributeMaxDynamicSharedMemorySize, SMEM_BYTES);

    float* d_WliT; cudaGetSymbolAddress((void**)&d_WliT, g_WliT);

    wsplit_kernel<<<N2 * N1 / 256, 256>>>(W_lif);
    spkconv_kernel<<<(int)((size_t)T_STEPS * BATCH * N2 / 4 / 256), 256>>>(spk);
    transpose_kernel<<<dim3(16, 8), dim3(32, 8)>>>(W_li, d_WliT, N2, N1);
    mma_scan_kernel<<<BATCH * 8, 128, SMEM_BYTES>>>(b_lif);
    tail_kernel<<<BATCH, 256>>>(b_li, W1, b1, W2, b2, ln_g, ln_b, out);
}

// round 14
// speedup vs baseline: 1.3234x; 1.1385x over previous
#include <cuda_runtime.h>
#include <cuda_fp16.h>
#include <mma.h>
#include <cstdint>

using namespace nvcuda;

#define T_STEPS 512
#define BATCH   256
#define N1      512
#define N2      256
#define N3      64
#define N4      784

// Scratch (no allocations allowed)
__device__ __half  g_Wh[2 * N2 * N1];                 // W_lif 2-way fp16 split: [s][i][n]
__device__ __half  g_spkh[(size_t)T_STEPS * BATCH * N2];  // spikes as fp16 (64 MB)
__device__ float   g_WliT[N1 * N2];                   // W_li^T : [k][j] (kept for layout compat)
__device__ float   g_S[BATCH * N1];                   // weighted spike sums
__device__ float   g_x[BATCH * N2];                   // x = S @ W_li^T + SW*b_li

__device__ __forceinline__ uint32_t smem_u32(const void* p) {
    uint32_t a;
    asm("{ .reg .u64 t; cvta.to.shared.u64 t, %1; cvt.u32.u64 %0, t; }" : "=r"(a) : "l"(p));
    return a;
}

// ---------------------------------------------------------------------------
// Kernel 1: split W_lif[n][i] into 2 fp16 components stored as [s][i][n]
// ---------------------------------------------------------------------------
__global__ void __launch_bounds__(256) wsplit_kernel(const float* __restrict__ W) {
    int idx = blockIdx.x * 256 + threadIdx.x;        // over i*512 + n
    int i = idx >> 9, n = idx & 511;
    float w = W[n * N2 + i];
    __half h1 = __float2half_rn(w);
    float r = w - __half2float(h1);
    __half h2 = __float2half_rn(r);
    g_Wh[idx]            = h1;                       // split 0
    g_Wh[N2 * N1 + idx]  = h2;                       // split 1
}

// ---------------------------------------------------------------------------
// Kernel 2: convert spikes fp32 -> fp16 (exact: values are 0/1)
// ---------------------------------------------------------------------------
__global__ void __launch_bounds__(256) spkconv_kernel(const float* __restrict__ spk) {
    size_t idx = (size_t)blockIdx.x * 256 + threadIdx.x;   // x4 elems
    float4 v = reinterpret_cast<const float4*>(spk)[idx];
    __half2 a = __floats2half2_rn(v.x, v.y);
    __half2 b = __floats2half2_rn(v.z, v.w);
    uint32_t* dst = reinterpret_cast<uint32_t*>(g_spkh);
    dst[idx * 2]     = *reinterpret_cast<uint32_t*>(&a);
    dst[idx * 2 + 1] = *reinterpret_cast<uint32_t*>(&b);
}

// ---------------------------------------------------------------------------
// smem layout (bytes), per block (N-chunk = 64 neurons):
//   W resident : [2][256][72] fp16 = 73728            @ 0
//   A buffers  : 2 x [128][72] fp16 = 2 x 18432       @ 73728, 92160
//   C overlay  : [64][132] fp32 (col-major [n][t]) = 33792 @ 73728 (over A)
//   total = 110592  -> 2 blocks/SM, 4 MMA warps each (warp tile 64t x 32n)
// ---------------------------------------------------------------------------
#define W_BYTES     73728
#define A_OFF(buf)  (W_BYTES + (buf) * 18432)
#define SMEM_BYTES  110592

// async-load one A k-chunk: spk[t0..t0+128, kc*64..+64] fp16 (16 KB), 128 thr
__device__ __forceinline__ void prefetch_A(int b, int t0, int kc,
                                           uint32_t smA, int tid) {
    #pragma unroll
    for (int j = 0; j < 8; j++) {
        int c16 = tid + j * 128;
        int r = c16 >> 3, cc = c16 & 7;
        const char* g = reinterpret_cast<const char*>(g_spkh)
            + ((((size_t)(t0 + r)) * BATCH + b) * N2 + kc * 64 + cc * 8) * 2;
        asm volatile("cp.async.cg.shared.global [%0], [%1], 16;"
                     :: "r"(smA + r * 144 + cc * 16), "l"(g));
    }
    asm volatile("cp.async.commit_group;" ::: "memory");
}

// ---------------------------------------------------------------------------
// Kernel 4: WMMA current GEMM (W resident in smem) + fused LIF scan.
// (byte-identical to R13 — proven at 196 us, tensor 57%)
// ---------------------------------------------------------------------------
__global__ void __launch_bounds__(128, 2) mma_scan_kernel(const float* __restrict__ b_lif) {
    extern __shared__ char sm[];
    const __half* Wsm = reinterpret_cast<const __half*>(sm);   // [2][256][72]
    float* Csm = reinterpret_cast<float*>(sm + W_BYTES);       // [64][132] col-major overlay

    const int tid  = threadIdx.x;
    const int warp = tid >> 5;
    const int b      = blockIdx.x >> 3;
    const int nchunk = blockIdx.x & 7;
    const int nbase  = nchunk * 64;
    const int wm = warp >> 1, wn = warp & 1;     // 2m x 2n

    const uint32_t smbase = smem_u32(sm);

    // ---- load resident W chunk: both splits, [s][i=256][n=64], stride 72 halves
    #pragma unroll
    for (int j = 0; j < 32; j++) {
        int c = tid + j * 128;                    // 4096 x 16B chunks
        int s = c >> 11, rem = c & 2047;
        int i = rem >> 3, cc = rem & 7;
        const char* g = reinterpret_cast<const char*>(g_Wh)
            + (((size_t)(s * N2 + i)) * N1 + nbase + cc * 8) * 2;
        asm volatile("cp.async.cg.shared.global [%0], [%1], 16;"
                     :: "r"(smbase + (uint32_t)(s * 36864 + i * 144 + cc * 16)), "l"(g));
    }
    asm volatile("cp.async.commit_group;" ::: "memory");
    asm volatile("cp.async.wait_group 0;" ::: "memory");
    __syncthreads();

    wmma::fragment<wmma::accumulator, 16, 16, 16, float> c[4][2];

    const float bl = (tid < 64) ? b_lif[nbase + tid] : 0.0f;
    const float inv_beta = 1.0f / 0.95f;
    const float wnorm    = 1.0f / 25.6f;
    float p = 0.95f;                                 // beta_li^T via 9 squarings
    #pragma unroll
    for (int k = 0; k < 9; k++) p *= p;

    float mem = 0.0f, S = 0.0f;

    for (int tt = 0; tt < 4; tt++) {
        const int t0 = tt * 128;
        #pragma unroll
        for (int mi = 0; mi < 4; mi++)
            #pragma unroll
            for (int ni = 0; ni < 2; ni++)
                wmma::fill_fragment(c[mi][ni], 0.0f);

        prefetch_A(b, t0, 0, smbase + A_OFF(0), tid);

        #pragma unroll
        for (int kc = 0; kc < 4; kc++) {
            const int cur = kc & 1;
            __syncthreads();              // A buf[cur^1] consumed by prev MMA
            if (kc < 3) {
                prefetch_A(b, t0, kc + 1, smbase + A_OFF(cur ^ 1), tid);
                asm volatile("cp.async.wait_group 1;" ::: "memory");
            } else {
                asm volatile("cp.async.wait_group 0;" ::: "memory");
            }
            __syncthreads();              // A buf[cur] visible

            const __half* Asm = reinterpret_cast<const __half*>(sm + A_OFF(cur));

            #pragma unroll
            for (int ks = 0; ks < 4; ks++) {
                wmma::fragment<wmma::matrix_a, 16, 16, 16, __half, wmma::row_major> a[4];
                #pragma unroll
                for (int mi = 0; mi < 4; mi++)
                    wmma::load_matrix_sync(a[mi],
                        Asm + (wm * 64 + mi * 16) * 72 + ks * 16, 72);
                #pragma unroll
                for (int s = 0; s < 2; s++) {
                    #pragma unroll
                    for (int ni = 0; ni < 2; ni++) {
                        wmma::fragment<wmma::matrix_b, 16, 16, 16, __half, wmma::row_major> bf;
                        wmma::load_matrix_sync(bf,
                            Wsm + s * 18432 + (kc * 64 + ks * 16) * 72 + wn * 32 + ni * 16, 72);
                        #pragma unroll
                        for (int mi = 0; mi < 4; mi++)
                            wmma::mma_sync(c[mi][ni], a[mi], bf, c[mi][ni]);
                    }
                }
            }
        }
        __syncthreads();                             // GEMM done; A region free

        // store C col-major: element (t, n) -> Csm[n*132 + t]
        #pragma unroll
        for (int mi = 0; mi < 4; mi++)
            #pragma unroll
            for (int ni = 0; ni < 2; ni++)
                wmma::store_matrix_sync(
                    Csm + (wn * 32 + ni * 16) * 132 + (wm * 64 + mi * 16),
                    c[mi][ni], 132, wmma::mem_col_major);
        __syncthreads();

        // LIF scan: threads 0-63 own a neuron; 32 contiguous float4 reads
        if (tid < 64) {
            const float4* Crow = reinterpret_cast<const float4*>(Csm + (size_t)tid * 132);
            #pragma unroll 8
            for (int q = 0; q < 32; q++) {
                float4 v = Crow[q];
                #pragma unroll
                for (int e = 0; e < 4; e++) {
                    float cur = ((e == 0) ? v.x : (e == 1) ? v.y : (e == 2) ? v.z : v.w) + bl;
                    float rst = (mem > 1.0f) ? 1.0f : 0.0f;
                    mem = 0.9f * mem + cur - rst;
                    float wt = (1.0f - p) * wnorm;
                    if (mem > 1.0f) S += wt;
                    p *= inv_beta;
                }
            }
        }
        __syncthreads();                             // scan done before next A loads
    }

    if (tid < 64)
        g_S[(size_t)b * N1 + nbase + tid] = S;
}

// ---------------------------------------------------------------------------
// Kernel 5a: x = S @ W_li^T + SW*b_li — warp-per-output, 4 outputs/warp (ILP),
// grid = 256 b x 8 j-groups = 2048 blocks (full SM coverage).
// ---------------------------------------------------------------------------
__global__ void __launch_bounds__(256) tailx_kernel(const float* __restrict__ W_li,
                                                    const float* __restrict__ b_li) {
    __shared__ float sS[N1];
    const int b  = blockIdx.x >> 3;
    const int jg = blockIdx.x & 7;
    const int tid = threadIdx.x;
    const int warp = tid >> 5, lane = tid & 31;

    sS[tid]       = g_S[(size_t)b * N1 + tid];
    sS[tid + 256] = g_S[(size_t)b * N1 + 256 + tid];
    __syncthreads();

    float pw = 0.95f;
    #pragma unroll
    for (int k = 0; k < 9; k++) pw *= pw;
    const float SW = (512.0f - 19.0f * (1.0f - pw)) / 25.6f;

    const int j0 = jg * 32 + warp * 4;              // 4 outputs per warp
    const float4* sS4 = reinterpret_cast<const float4*>(sS);
    float acc[4] = {0.f, 0.f, 0.f, 0.f};
    #pragma unroll
    for (int it = 0; it < 4; it++) {
        const int k4 = it * 32 + lane;
        const float4 sv = sS4[k4];
        #pragma unroll
        for (int oo = 0; oo < 4; oo++) {
            const float4 wv = reinterpret_cast<const float4*>(
                W_li + (size_t)(j0 + oo) * N1)[k4];
            acc[oo] += wv.x * sv.x + wv.y * sv.y + wv.z * sv.z + wv.w * sv.w;
        }
    }
    #pragma unroll
    for (int oo = 0; oo < 4; oo++) {
        float a = acc[oo];
        #pragma unroll
        for (int d = 16; d > 0; d >>= 1) a += __shfl_xor_sync(0xffffffffu, a, d);
        if (lane == 0) g_x[(size_t)b * N2 + j0 + oo] = a + SW * b_li[j0 + oo];
    }
}

// ---------------------------------------------------------------------------
// Kernel 5b: MLP + layernorm — one 512-thread block per batch row.
// ---------------------------------------------------------------------------
__global__ void __launch_bounds__(512) tailmlp_kernel(
    const float* __restrict__ W1,  const float* __restrict__ b1,
    const float* __restrict__ W2,  const float* __restrict__ b2,
    const float* __restrict__ ln_g, const float* __restrict__ ln_b,
    float* __restrict__ out)
{
    __shared__ float sx[N2];
    __shared__ float sh[N3];
    __shared__ float sy[N4];
    __shared__ float sred[16];
    const int b = blockIdx.x, tid = threadIdx.x;
    const int warp = tid >> 5, lane = tid & 31;   // 16 warps

    if (tid < 256) sx[tid] = g_x[(size_t)b * N2 + tid];
    __syncthreads();

    // h[o] = relu(W1[o,:].x + b1[o]) — 4 outputs per warp (float2 lanes)
    const float2* sx2 = reinterpret_cast<const float2*>(sx);
    #pragma unroll
    for (int oo = 0; oo < 4; oo++) {
        int o = warp * 4 + oo;
        const float2* wrow = reinterpret_cast<const float2*>(W1 + (size_t)o * N2);
        float acc = 0.0f;
        #pragma unroll
        for (int it = 0; it < 4; it++) {
            int k2 = it * 32 + lane;
            float2 wv = wrow[k2], xv = sx2[k2];
            acc += wv.x * xv.x + wv.y * xv.y;
        }
        #pragma unroll
        for (int d = 16; d > 0; d >>= 1) acc += __shfl_xor_sync(0xffffffffu, acc, d);
        if (lane == 0) sh[o] = fmaxf(acc + b1[o], 0.0f);
    }
    __syncthreads();

    // y[o] = W2[o,:].h + b2[o] — warp-per-output, 49 per warp (indep iters)
    const float2* hh = reinterpret_cast<const float2*>(sh);
    float2 hv = hh[lane];
    #pragma unroll 2
    for (int g = 0; g < 49; g++) {
        int o = warp + g * 16;
        const float2* w2 = reinterpret_cast<const float2*>(W2 + (size_t)o * N3);
        float2 wv = w2[lane];
        float acc = wv.x * hv.x + wv.y * hv.y;
        #pragma unroll
        for (int d = 16; d > 0; d >>= 1) acc += __shfl_xor_sync(0xffffffffu, acc, d);
        if (lane == 0) sy[o] = acc + b2[o];
    }
    __syncthreads();

    // layernorm over 784 (512 threads, 16 warps)
    float s = 0.0f;
    for (int k = tid; k < N4; k += 512) s += sy[k];
    #pragma unroll
    for (int o = 16; o > 0; o >>= 1) s += __shfl_xor_sync(0xffffffffu, s, o);
    if (lane == 0) sred[warp] = s;
    __syncthreads();
    if (tid < 32) {
        float v = (tid < 16) ? sred[tid] : 0.0f;
        #pragma unroll
        for (int o = 8; o > 0; o >>= 1) v += __shfl_xor_sync(0xffffffffu, v, o);
        if (tid == 0) sred[0] = v;
    }
    __syncthreads();
    const float mu = sred[0] / (float)N4;
    __syncthreads();

    float s2 = 0.0f;
    for (int k = tid; k < N4; k += 512) { float d = sy[k] - mu; s2 += d * d; }
    #pragma unroll
    for (int o = 16; o > 0; o >>= 1) s2 += __shfl_xor_sync(0xffffffffu, s2, o);
    if (lane == 0) sred[warp] = s2;
    __syncthreads();
    if (tid < 32) {
        float v = (tid < 16) ? sred[tid] : 0.0f;
        #pragma unroll
        for (int o = 8; o > 0; o >>= 1) v += __shfl_xor_sync(0xffffffffu, v, o);
        if (tid == 0) sred[0] = v;
    }
    __syncthreads();
    const float var  = sred[0] / (float)N4;
    const float rstd = rsqrtf(var + 1e-5f);

    for (int k = tid; k < N4; k += 512)
        out[(size_t)b * N4 + k] = (sy[k] - mu) * rstd * ln_g[k] + ln_b[k];
}

// ---------------------------------------------------------------------------
extern "C" void kernel_launch(void* const* d_in, const int* in_sizes, int n_in,
                              void* d_out, int out_size) {
    const float* spk   = (const float*)d_in[0];
    const float* W_lif = (const float*)d_in[1];
    const float* b_lif = (const float*)d_in[2];
    const float* W_li  = (const float*)d_in[3];
    const float* b_li  = (const float*)d_in[4];
    const float* W1    = (const float*)d_in[5];
    const float* b1    = (const float*)d_in[6];
    const float* W2    = (const float*)d_in[7];
    const float* b2    = (const float*)d_in[8];
    const float* ln_g  = (const float*)d_in[9];
    const float* ln_b  = (const float*)d_in[10];
    float* out = (float*)d_out;

    cudaFuncSetAttribute(mma_scan_kernel, cudaFuncAttributeMaxDynamicSharedMemorySize, SMEM_BYTES);

    wsplit_kernel<<<N2 * N1 / 256, 256>>>(W_lif);
    spkconv_kernel<<<(int)((size_t)T_STEPS * BATCH * N2 / 4 / 256), 256>>>(spk);
    mma_scan_kernel<<<BATCH * 8, 128, SMEM_BYTES>>>(b_lif);
    tailx_kernel<<<BATCH * 8, 256>>>(W_li, b_li);
    tailmlp_kernel<<<BATCH, 512>>>(W1, b1, W2, b2, ln_g, ln_b, out);
}